// round 1
// baseline (speedup 1.0000x reference)
#include <cuda_runtime.h>
#include <math.h>

// Problem constants
#define TT  4096      // tokens = B*S
#define HH  1024      // hidden
#define EE  8         // experts
#define FF  2048      // ffn dim
#define CAP 4096      // max pairs per expert (<= T)

// ---------------- scratch (device globals; no allocation allowed) ----------------
__device__ int   g_count[EE];
__device__ int   g_plist[EE * CAP];            // packed id = token*2 + slot
__device__ float g_wpair[TT * 2];              // routing weight per packed id
__device__ __align__(16) float g_inner[(size_t)TT * 2 * FF];  // 64 MiB

// ---------------- zero out + counters ----------------
__global__ void zero_kernel(float4* out4, int n4) {
    int i = blockIdx.x * blockDim.x + threadIdx.x;
    if (i < n4) out4[i] = make_float4(0.f, 0.f, 0.f, 0.f);
    if (blockIdx.x == 0 && threadIdx.x < EE) g_count[threadIdx.x] = 0;
}

// ---------------- router: logits -> top2 -> renorm -> scatter ----------------
__global__ __launch_bounds__(128) void router_kernel(const float* __restrict__ x,
                                                     const float* __restrict__ gw) {
    int t   = blockIdx.x;
    int tid = threadIdx.x;
    const float* xp = x + (size_t)t * HH;

    double part[EE];
#pragma unroll
    for (int e = 0; e < EE; e++) part[e] = 0.0;
#pragma unroll
    for (int s = 0; s < HH / 128; s++) {
        int h = tid + s * 128;
        double xv = (double)xp[h];
#pragma unroll
        for (int e = 0; e < EE; e++) part[e] += xv * (double)gw[h * EE + e];
    }

    __shared__ double red[EE][128];
#pragma unroll
    for (int e = 0; e < EE; e++) red[e][tid] = part[e];
    __syncthreads();
    for (int st = 64; st > 0; st >>= 1) {
        if (tid < st) {
#pragma unroll
            for (int e = 0; e < EE; e++) red[e][tid] += red[e][tid + st];
        }
        __syncthreads();
    }

    if (tid == 0) {
        double l[EE];
#pragma unroll
        for (int e = 0; e < EE; e++) l[e] = red[e][0];
        // top-1 (ties -> lowest index, strict >)
        int i0 = 0;
        for (int e = 1; e < EE; e++) if (l[e] > l[i0]) i0 = e;
        // top-2
        int i1 = (i0 == 0) ? 1 : 0;
        for (int e = 0; e < EE; e++) if (e != i0 && l[e] > l[i1]) i1 = e;
        // renormalized softmax over the two selected logits
        double d  = exp(l[i1] - l[i0]);
        float  w0 = (float)(1.0 / (1.0 + d));
        float  w1 = (float)(d   / (1.0 + d));

        int p0 = atomicAdd(&g_count[i0], 1);
        g_plist[i0 * CAP + p0] = t * 2;
        int p1 = atomicAdd(&g_count[i1], 1);
        g_plist[i1 * CAP + p1] = t * 2 + 1;
        g_wpair[t * 2]     = w0;
        g_wpair[t * 2 + 1] = w1;
    }
}

// ---------------- stage 1: inner = silu(x@Wup) * (x@Wgate), gathered rows ----------------
#define S1_BM 128
#define S1_BN 64
#define S1_BK 16

__global__ __launch_bounds__(256, 2) void stage1_kernel(const float* __restrict__ x,
                                                        const float* __restrict__ wup,
                                                        const float* __restrict__ wgate) {
    const int e   = blockIdx.y >> 5;
    const int mt  = blockIdx.y & 31;
    const int cnt = g_count[e];
    const int m0  = mt * S1_BM;
    if (m0 >= cnt) return;
    const int f0 = blockIdx.x * S1_BN;

    __shared__ __align__(16) float As[S1_BK][S1_BM];
    __shared__ __align__(16) float Bu[S1_BK][S1_BN];
    __shared__ __align__(16) float Bg[S1_BK][S1_BN];
    __shared__ int rid[S1_BM];

    const int tid = threadIdx.x;
    if (tid < S1_BM) {
        int r = m0 + tid;
        rid[tid] = (r < cnt) ? g_plist[e * CAP + r] : -1;
    }
    __syncthreads();

    // A-load mapping: 2 threads per row, 8 k-floats each
    const int arow  = tid >> 1;
    const int akseg = (tid & 1) * 8;
    const int aid   = rid[arow];
    const float* xrow = x + (size_t)(aid < 0 ? 0 : (aid >> 1)) * HH;

    // W-load mapping: 16 k-rows x 64 cols, 1 float4 per thread per matrix
    const int wrow = tid >> 4;
    const int wcol = (tid & 15) * 4;
    const float* wub = wup   + (size_t)e * HH * FF + (size_t)wrow * FF + f0 + wcol;
    const float* wgb = wgate + (size_t)e * HH * FF + (size_t)wrow * FF + f0 + wcol;

    // micro-tile mapping: 8 rows x 4 cols per thread
    const int tm = (tid & 15) * 8;
    const int tn = (tid >> 4) * 4;

    float accU[8][4], accG[8][4];
#pragma unroll
    for (int i = 0; i < 8; i++)
#pragma unroll
        for (int j = 0; j < 4; j++) { accU[i][j] = 0.f; accG[i][j] = 0.f; }

    for (int k0 = 0; k0 < HH; k0 += S1_BK) {
        float4 a0 = *(const float4*)(xrow + k0 + akseg);
        float4 a1 = *(const float4*)(xrow + k0 + akseg + 4);
        float4 u  = *(const float4*)(wub + (size_t)k0 * FF);
        float4 g  = *(const float4*)(wgb + (size_t)k0 * FF);
        __syncthreads();
        As[akseg + 0][arow] = a0.x; As[akseg + 1][arow] = a0.y;
        As[akseg + 2][arow] = a0.z; As[akseg + 3][arow] = a0.w;
        As[akseg + 4][arow] = a1.x; As[akseg + 5][arow] = a1.y;
        As[akseg + 6][arow] = a1.z; As[akseg + 7][arow] = a1.w;
        *(float4*)&Bu[wrow][wcol] = u;
        *(float4*)&Bg[wrow][wcol] = g;
        __syncthreads();
#pragma unroll
        for (int kk = 0; kk < S1_BK; kk++) {
            float a[8], bu[4], bg[4];
            *(float4*)&a[0]  = *(const float4*)&As[kk][tm];
            *(float4*)&a[4]  = *(const float4*)&As[kk][tm + 4];
            *(float4*)&bu[0] = *(const float4*)&Bu[kk][tn];
            *(float4*)&bg[0] = *(const float4*)&Bg[kk][tn];
#pragma unroll
            for (int i = 0; i < 8; i++)
#pragma unroll
                for (int j = 0; j < 4; j++) {
                    accU[i][j] += a[i] * bu[j];
                    accG[i][j] += a[i] * bg[j];
                }
        }
    }

    // epilogue: silu(up) * gate -> g_inner[id][f]
#pragma unroll
    for (int i = 0; i < 8; i++) {
        int r = m0 + tm + i;
        if (r < cnt) {
            int id = rid[tm + i];
            float v[4];
#pragma unroll
            for (int j = 0; j < 4; j++) {
                float uu = accU[i][j];
                float s  = uu / (1.f + __expf(-uu));
                v[j] = s * accG[i][j];
            }
            *(float4*)&g_inner[(size_t)id * FF + f0 + tn] = *(float4*)v;
        }
    }
}

// ---------------- stage 2: out += w * (inner @ Wdown), gathered rows ----------------
#define S2_BM 128
#define S2_BN 128
#define S2_BK 16

__global__ __launch_bounds__(256, 2) void stage2_kernel(const float* __restrict__ wdown,
                                                        float* __restrict__ out) {
    const int e   = blockIdx.y >> 5;
    const int mt  = blockIdx.y & 31;
    const int cnt = g_count[e];
    const int m0  = mt * S2_BM;
    if (m0 >= cnt) return;
    const int h0 = blockIdx.x * S2_BN;

    __shared__ __align__(16) float As[S2_BK][S2_BM];
    __shared__ __align__(16) float Bd[S2_BK][S2_BN];
    __shared__ int rid[S2_BM];

    const int tid = threadIdx.x;
    if (tid < S2_BM) {
        int r = m0 + tid;
        rid[tid] = (r < cnt) ? g_plist[e * CAP + r] : -1;
    }
    __syncthreads();

    const int arow  = tid >> 1;
    const int akseg = (tid & 1) * 8;
    const int aid   = rid[arow];
    const float* arp = g_inner + (size_t)(aid < 0 ? 0 : aid) * FF;

    const float* wdb = wdown + (size_t)e * FF * HH + h0;

    const int tm = (tid & 15) * 8;
    const int tn = (tid >> 4) * 8;

    float acc[8][8];
#pragma unroll
    for (int i = 0; i < 8; i++)
#pragma unroll
        for (int j = 0; j < 8; j++) acc[i][j] = 0.f;

    const int v0 = tid, v1 = tid + 256;          // 512 float4s in the 16x128 B tile
    const int b0r = v0 >> 5, b0c = (v0 & 31) * 4;
    const int b1r = v1 >> 5, b1c = (v1 & 31) * 4;

    for (int k0 = 0; k0 < FF; k0 += S2_BK) {
        float4 a0 = *(const float4*)(arp + k0 + akseg);
        float4 a1 = *(const float4*)(arp + k0 + akseg + 4);
        float4 b0 = *(const float4*)(wdb + (size_t)(k0 + b0r) * HH + b0c);
        float4 b1 = *(const float4*)(wdb + (size_t)(k0 + b1r) * HH + b1c);
        __syncthreads();
        As[akseg + 0][arow] = a0.x; As[akseg + 1][arow] = a0.y;
        As[akseg + 2][arow] = a0.z; As[akseg + 3][arow] = a0.w;
        As[akseg + 4][arow] = a1.x; As[akseg + 5][arow] = a1.y;
        As[akseg + 6][arow] = a1.z; As[akseg + 7][arow] = a1.w;
        *(float4*)&Bd[b0r][b0c] = b0;
        *(float4*)&Bd[b1r][b1c] = b1;
        __syncthreads();
#pragma unroll
        for (int kk = 0; kk < S2_BK; kk++) {
            float a[8], b[8];
            *(float4*)&a[0] = *(const float4*)&As[kk][tm];
            *(float4*)&a[4] = *(const float4*)&As[kk][tm + 4];
            *(float4*)&b[0] = *(const float4*)&Bd[kk][tn];
            *(float4*)&b[4] = *(const float4*)&Bd[kk][tn + 4];
#pragma unroll
            for (int i = 0; i < 8; i++)
#pragma unroll
                for (int j = 0; j < 8; j++) acc[i][j] += a[i] * b[j];
        }
    }

    // epilogue: scale by routing weight, accumulate (exactly 2 adds/elem -> deterministic)
#pragma unroll
    for (int i = 0; i < 8; i++) {
        int r = m0 + tm + i;
        if (r < cnt) {
            int   id = rid[tm + i];
            float w  = g_wpair[id];
            float* op = out + (size_t)(id >> 1) * HH + h0 + tn;
#pragma unroll
            for (int j = 0; j < 8; j++) atomicAdd(&op[j], w * acc[i][j]);
        }
    }
}

// ---------------- launch ----------------
extern "C" void kernel_launch(void* const* d_in, const int* in_sizes, int n_in,
                              void* d_out, int out_size) {
    const float* x  = (const float*)d_in[0];   // hidden_states [T, H]
    const float* gw = (const float*)d_in[1];   // gate_w [H, E]
    const float* wu = (const float*)d_in[2];   // w_up   [E, H, F]
    const float* wg = (const float*)d_in[3];   // w_gate [E, H, F]
    const float* wd = (const float*)d_in[4];   // w_down [E, F, H]
    float* out = (float*)d_out;

    int n4 = out_size / 4;
    zero_kernel<<<(n4 + 255) / 256, 256>>>((float4*)out, n4);
    router_kernel<<<TT, 128>>>(x, gw);
    stage1_kernel<<<dim3(FF / S1_BN, EE * (CAP / S1_BM)), 256>>>(x, wu, wg);
    stage2_kernel<<<dim3(HH / S2_BN, EE * (CAP / S2_BM)), 256>>>(wd, out);
}

// round 3
// speedup vs baseline: 2.1361x; 2.1361x over previous
#include <cuda_runtime.h>
#include <cuda_bf16.h>
#include <math.h>
#include <stdint.h>

#define TT 4096
#define HH 1024
#define EE 8
#define FF 2048
#define CAP 4096
#define NW (EE * HH * FF)   // 16777216 (w_up / w_gate)
#define ND (EE * FF * HH)   // 16777216 (w_down)

// ---------------- scratch (device globals) ----------------
__device__ int   g_count[EE];
__device__ int   g_plist[EE * CAP];                 // packed id = token*2 + slot
__device__ float g_wpair[TT * 2];
__device__ __align__(16) __nv_bfloat16 g_xh[TT * HH], g_xl[TT * HH];
__device__ __align__(16) __nv_bfloat16 g_wuh[NW], g_wul[NW];
__device__ __align__(16) __nv_bfloat16 g_wgh[NW], g_wgl[NW];
__device__ __align__(16) __nv_bfloat16 g_wdh[ND], g_wdl[ND];
__device__ __align__(16) __nv_bfloat16 g_ih[(size_t)TT * 2 * FF], g_il[(size_t)TT * 2 * FF];

// ---------------- helpers ----------------
__device__ __forceinline__ uint32_t smem_u32(const void* p) {
    uint32_t a;
    asm("{ .reg .u64 t; cvta.to.shared.u64 t, %1; cvt.u32.u64 %0, t; }" : "=r"(a) : "l"(p));
    return a;
}
__device__ __forceinline__ void splitf(float f, uint32_t& h, uint32_t& l) {
    __nv_bfloat16 hb = __float2bfloat16_rn(f);
    float rf = f - __bfloat162float(hb);
    __nv_bfloat16 lb = __float2bfloat16_rn(rf);
    h = (uint32_t)__bfloat16_as_ushort(hb);
    l = (uint32_t)__bfloat16_as_ushort(lb);
}

#define CP16(dst, src)  asm volatile("cp.async.cg.shared.global [%0], [%1], 16;" :: "r"(dst), "l"(src))
#define CPCOMMIT()      asm volatile("cp.async.commit_group;" ::: "memory")
#define CPWAIT1()       asm volatile("cp.async.wait_group 1;" ::: "memory")

#define LDSM4(r, a)                                                                   \
    asm volatile("ldmatrix.sync.aligned.m8n8.x4.shared.b16 {%0,%1,%2,%3}, [%4];"      \
        : "=r"((r)[0]), "=r"((r)[1]), "=r"((r)[2]), "=r"((r)[3]) : "r"(a))
#define LDSM4T(r, a)                                                                  \
    asm volatile("ldmatrix.sync.aligned.m8n8.x4.trans.shared.b16 {%0,%1,%2,%3}, [%4];"\
        : "=r"((r)[0]), "=r"((r)[1]), "=r"((r)[2]), "=r"((r)[3]) : "r"(a))

__device__ __forceinline__ void mma_bf16(float* d, const uint32_t* a, uint32_t b0, uint32_t b1) {
    asm volatile(
        "mma.sync.aligned.m16n8k16.row.col.f32.bf16.bf16.f32 "
        "{%0,%1,%2,%3},{%4,%5,%6,%7},{%8,%9},{%0,%1,%2,%3};"
        : "+f"(d[0]), "+f"(d[1]), "+f"(d[2]), "+f"(d[3])
        : "r"(a[0]), "r"(a[1]), "r"(a[2]), "r"(a[3]), "r"(b0), "r"(b1));
}

// ---------------- zero ----------------
__global__ void zero_kernel(float4* out4, int n4) {
    int i = blockIdx.x * blockDim.x + threadIdx.x;
    if (i < n4) out4[i] = make_float4(0.f, 0.f, 0.f, 0.f);
    if (blockIdx.x == 0 && threadIdx.x < EE) g_count[threadIdx.x] = 0;
}

// ---------------- fp32 -> bf16 hi/lo split prepass ----------------
__global__ __launch_bounds__(256) void split_kernel(const float4* __restrict__ src, int which, int n4) {
    int i = blockIdx.x * blockDim.x + threadIdx.x;
    if (i >= n4) return;
    __nv_bfloat16 *hp, *lp;
    switch (which) {
        case 0: hp = g_wuh; lp = g_wul; break;
        case 1: hp = g_wgh; lp = g_wgl; break;
        case 2: hp = g_wdh; lp = g_wdl; break;
        default: hp = g_xh; lp = g_xl; break;
    }
    float4 v = src[i];
    uint32_t h0, h1, h2, h3, l0, l1, l2, l3;
    splitf(v.x, h0, l0); splitf(v.y, h1, l1);
    splitf(v.z, h2, l2); splitf(v.w, h3, l3);
    ((uint2*)hp)[i] = make_uint2(h0 | (h1 << 16), h2 | (h3 << 16));
    ((uint2*)lp)[i] = make_uint2(l0 | (l1 << 16), l2 | (l3 << 16));
}

// ---------------- router (fp64 logits -> top2 -> renorm -> scatter) ----------------
__global__ __launch_bounds__(128) void router_kernel(const float* __restrict__ x,
                                                     const float* __restrict__ gw) {
    int t = blockIdx.x, tid = threadIdx.x;
    const float* xp = x + (size_t)t * HH;
    double part[EE];
#pragma unroll
    for (int e = 0; e < EE; e++) part[e] = 0.0;
#pragma unroll
    for (int s = 0; s < HH / 128; s++) {
        int h = tid + s * 128;
        double xv = (double)xp[h];
#pragma unroll
        for (int e = 0; e < EE; e++) part[e] += xv * (double)gw[h * EE + e];
    }
    __shared__ double red[EE][128];
#pragma unroll
    for (int e = 0; e < EE; e++) red[e][tid] = part[e];
    __syncthreads();
    for (int st = 64; st > 0; st >>= 1) {
        if (tid < st) {
#pragma unroll
            for (int e = 0; e < EE; e++) red[e][tid] += red[e][tid + st];
        }
        __syncthreads();
    }
    if (tid == 0) {
        double l[EE];
#pragma unroll
        for (int e = 0; e < EE; e++) l[e] = red[e][0];
        int i0 = 0;
        for (int e = 1; e < EE; e++) if (l[e] > l[i0]) i0 = e;
        int i1 = (i0 == 0) ? 1 : 0;
        for (int e = 0; e < EE; e++) if (e != i0 && l[e] > l[i1]) i1 = e;
        double d  = exp(l[i1] - l[i0]);
        float  w0 = (float)(1.0 / (1.0 + d));
        float  w1 = (float)(d / (1.0 + d));
        int p0 = atomicAdd(&g_count[i0], 1);
        g_plist[i0 * CAP + p0] = t * 2;
        int p1 = atomicAdd(&g_count[i1], 1);
        g_plist[i1 * CAP + p1] = t * 2 + 1;
        g_wpair[t * 2]     = w0;
        g_wpair[t * 2 + 1] = w1;
    }
}

// ================= stage 1: inner = silu(X@Wup) * (X@Wgate) (bf16x3 mma) =================
// BM=128, BN=64, BK=32. 8 warps = 4m x 2n, warp tile 32x32.
// SMEM buffer (38912B): A_h@0 [128][40]b16, A_l@10240, BU_h@20480 [32][72]b16,
//                       BU_l@25088, BG_h@29696, BG_l@34304.
#define S1_BUF 38912u
#define S2_BUF 29696u
#define SMEM1 (2 * S1_BUF)
#define SMEM2 (2 * S2_BUF)

__global__ __launch_bounds__(256, 2) void stage1_mma() {
    const int e   = blockIdx.y >> 5;
    const int mt  = blockIdx.y & 31;
    const int cnt = g_count[e];
    const int m0  = mt * 128;
    if (m0 >= cnt) return;
    const int f0   = blockIdx.x * 64;
    const int tid  = threadIdx.x;
    const int lane = tid & 31;
    const int wid  = tid >> 5;
    const int wm   = wid & 3, wn = wid >> 2;

    __shared__ int rid_s[128];
    extern __shared__ char dsm[];
    const uint32_t sb = smem_u32(dsm);

    if (tid < 128) {
        int r = m0 + tid;
        rid_s[tid] = (r < cnt) ? g_plist[e * CAP + r] : 0;
    }
    __syncthreads();

    // ---- load mappings ----
    const int arow = tid >> 1, ahalf = tid & 1;
    const __nv_bfloat16* axh = g_xh + (size_t)(rid_s[arow] >> 1) * HH + ahalf * 16;
    const __nv_bfloat16* axl = g_xl + (size_t)(rid_s[arow] >> 1) * HH + ahalf * 16;
    const uint32_t adst = sb + arow * 80 + ahalf * 32;

    const int brow = tid >> 3, bseg = tid & 7;
    const size_t bg0 = ((size_t)e * HH + brow) * FF + f0 + bseg * 8;
    const uint32_t bdst = sb + brow * 144 + bseg * 16;

    // ---- accumulators ----
    float aU[2][4][4], aG[2][4][4];
#pragma unroll
    for (int i = 0; i < 2; i++)
#pragma unroll
        for (int j = 0; j < 4; j++)
#pragma unroll
            for (int q = 0; q < 4; q++) { aU[i][j][q] = 0.f; aG[i][j][q] = 0.f; }

#define S1_ISSUE(s) do {                                                   \
    int _k0 = (s) * 32;                                                    \
    uint32_t _bo = ((s) & 1) * S1_BUF;                                     \
    CP16(adst + _bo,              axh + _k0);                              \
    CP16(adst + _bo + 16,         axh + _k0 + 8);                          \
    CP16(adst + _bo + 10240,      axl + _k0);                              \
    CP16(adst + _bo + 10240 + 16, axl + _k0 + 8);                          \
    size_t _go = bg0 + (size_t)_k0 * FF;                                   \
    CP16(bdst + _bo + 20480, g_wuh + _go);                                 \
    CP16(bdst + _bo + 25088, g_wul + _go);                                 \
    CP16(bdst + _bo + 29696, g_wgh + _go);                                 \
    CP16(bdst + _bo + 34304, g_wgl + _go);                                 \
} while (0)

    // ldmatrix address bases
    uint32_t aab[2];
#pragma unroll
    for (int i = 0; i < 2; i++)
        aab[i] = sb + (wm * 32 + i * 16 + (lane & 15)) * 80 + (lane >> 4) * 16;
    const uint32_t bab = sb + 20480 + (lane & 15) * 144 + (wn * 32 + (lane >> 4) * 8) * 2;

    S1_ISSUE(0); CPCOMMIT();
    S1_ISSUE(1); CPCOMMIT();

    for (int s = 0; s < HH / 32; s++) {
        CPWAIT1();
        __syncthreads();
        const uint32_t bo = (s & 1) * S1_BUF;
#pragma unroll
        for (int kk = 0; kk < 32; kk += 16) {
            uint32_t ah[2][4], al[2][4];
#pragma unroll
            for (int i = 0; i < 2; i++) {
                uint32_t aa = aab[i] + bo + kk * 2;
                LDSM4(ah[i], aa);
                LDSM4(al[i], aa + 10240);
            }
#pragma unroll
            for (int jp = 0; jp < 2; jp++) {
                uint32_t ba = bab + bo + kk * 144 + jp * 32;
                uint32_t bh[4], bl[4];
                LDSM4T(bh, ba);            // BU hi
                LDSM4T(bl, ba + 4608);     // BU lo
#pragma unroll
                for (int i = 0; i < 2; i++)
#pragma unroll
                    for (int j2 = 0; j2 < 2; j2++) {
                        float* d = aU[i][jp * 2 + j2];
                        mma_bf16(d, ah[i], bh[2 * j2], bh[2 * j2 + 1]);
                        mma_bf16(d, ah[i], bl[2 * j2], bl[2 * j2 + 1]);
                        mma_bf16(d, al[i], bh[2 * j2], bh[2 * j2 + 1]);
                    }
                LDSM4T(bh, ba + 9216);     // BG hi
                LDSM4T(bl, ba + 13824);    // BG lo
#pragma unroll
                for (int i = 0; i < 2; i++)
#pragma unroll
                    for (int j2 = 0; j2 < 2; j2++) {
                        float* d = aG[i][jp * 2 + j2];
                        mma_bf16(d, ah[i], bh[2 * j2], bh[2 * j2 + 1]);
                        mma_bf16(d, ah[i], bl[2 * j2], bl[2 * j2 + 1]);
                        mma_bf16(d, al[i], bh[2 * j2], bh[2 * j2 + 1]);
                    }
            }
        }
        __syncthreads();
        if (s + 2 < HH / 32) S1_ISSUE(s + 2);
        CPCOMMIT();
    }

    // ---- epilogue: silu(U)*G -> inner hi/lo planes ----
    const int er = wm * 32 + (lane >> 2);
    const int ec = f0 + wn * 32 + 2 * (lane & 3);
#pragma unroll
    for (int i = 0; i < 2; i++)
#pragma unroll
        for (int half = 0; half < 2; half++) {
            int rr = er + i * 16 + half * 8;
            if (m0 + rr < cnt) {
                int id = rid_s[rr];
                size_t o = (size_t)id * FF + ec;
#pragma unroll
                for (int j = 0; j < 4; j++) {
                    float u0 = aU[i][j][half * 2 + 0], u1 = aU[i][j][half * 2 + 1];
                    float g0 = aG[i][j][half * 2 + 0], g1 = aG[i][j][half * 2 + 1];
                    float v0 = u0 / (1.f + __expf(-u0)) * g0;
                    float v1 = u1 / (1.f + __expf(-u1)) * g1;
                    uint32_t h0, l0, h1, l1;
                    splitf(v0, h0, l0); splitf(v1, h1, l1);
                    *(uint32_t*)(g_ih + o + j * 8) = h0 | (h1 << 16);
                    *(uint32_t*)(g_il + o + j * 8) = l0 | (l1 << 16);
                }
            }
        }
}

// ================= stage 2: out += w * (inner @ Wdown) (bf16x3 mma) =================
// SMEM buffer (29696B): A_h@0, A_l@10240, B_h@20480, B_l@25088.
__global__ __launch_bounds__(256, 2) void stage2_mma(float* __restrict__ out) {
    const int e   = blockIdx.y >> 5;
    const int mt  = blockIdx.y & 31;
    const int cnt = g_count[e];
    const int m0  = mt * 128;
    if (m0 >= cnt) return;
    const int h0   = blockIdx.x * 64;
    const int tid  = threadIdx.x;
    const int lane = tid & 31;
    const int wid  = tid >> 5;
    const int wm   = wid & 3, wn = wid >> 2;

    __shared__ int rid_s[128];
    extern __shared__ char dsm[];
    const uint32_t sb = smem_u32(dsm);

    if (tid < 128) {
        int r = m0 + tid;
        rid_s[tid] = (r < cnt) ? g_plist[e * CAP + r] : 0;
    }
    __syncthreads();

    const int arow = tid >> 1, ahalf = tid & 1;
    const __nv_bfloat16* axh = g_ih + (size_t)rid_s[arow] * FF + ahalf * 16;
    const __nv_bfloat16* axl = g_il + (size_t)rid_s[arow] * FF + ahalf * 16;
    const uint32_t adst = sb + arow * 80 + ahalf * 32;

    const int brow = tid >> 3, bseg = tid & 7;
    const size_t bg0 = ((size_t)e * FF + brow) * HH + h0 + bseg * 8;
    const uint32_t bdst = sb + brow * 144 + bseg * 16;

    float acc[2][4][4];
#pragma unroll
    for (int i = 0; i < 2; i++)
#pragma unroll
        for (int j = 0; j < 4; j++)
#pragma unroll
            for (int q = 0; q < 4; q++) acc[i][j][q] = 0.f;

#define S2_ISSUE(s) do {                                                   \
    int _k0 = (s) * 32;                                                    \
    uint32_t _bo = ((s) & 1) * S2_BUF;                                     \
    CP16(adst + _bo,              axh + _k0);                              \
    CP16(adst + _bo + 16,         axh + _k0 + 8);                          \
    CP16(adst + _bo + 10240,      axl + _k0);                              \
    CP16(adst + _bo + 10240 + 16, axl + _k0 + 8);                          \
    size_t _go = bg0 + (size_t)_k0 * HH;                                   \
    CP16(bdst + _bo + 20480, g_wdh + _go);                                 \
    CP16(bdst + _bo + 25088, g_wdl + _go);                                 \
} while (0)

    uint32_t aab[2];
#pragma unroll
    for (int i = 0; i < 2; i++)
        aab[i] = sb + (wm * 32 + i * 16 + (lane & 15)) * 80 + (lane >> 4) * 16;
    const uint32_t bab = sb + 20480 + (lane & 15) * 144 + (wn * 32 + (lane >> 4) * 8) * 2;

    S2_ISSUE(0); CPCOMMIT();
    S2_ISSUE(1); CPCOMMIT();

    for (int s = 0; s < FF / 32; s++) {
        CPWAIT1();
        __syncthreads();
        const uint32_t bo = (s & 1) * S2_BUF;
#pragma unroll
        for (int kk = 0; kk < 32; kk += 16) {
            uint32_t ah[2][4], al[2][4];
#pragma unroll
            for (int i = 0; i < 2; i++) {
                uint32_t aa = aab[i] + bo + kk * 2;
                LDSM4(ah[i], aa);
                LDSM4(al[i], aa + 10240);
            }
#pragma unroll
            for (int jp = 0; jp < 2; jp++) {
                uint32_t ba = bab + bo + kk * 144 + jp * 32;
                uint32_t bh[4], bl[4];
                LDSM4T(bh, ba);
                LDSM4T(bl, ba + 4608);
#pragma unroll
                for (int i = 0; i < 2; i++)
#pragma unroll
                    for (int j2 = 0; j2 < 2; j2++) {
                        float* d = acc[i][jp * 2 + j2];
                        mma_bf16(d, ah[i], bh[2 * j2], bh[2 * j2 + 1]);
                        mma_bf16(d, ah[i], bl[2 * j2], bl[2 * j2 + 1]);
                        mma_bf16(d, al[i], bh[2 * j2], bh[2 * j2 + 1]);
                    }
            }
        }
        __syncthreads();
        if (s + 2 < FF / 32) S2_ISSUE(s + 2);
        CPCOMMIT();
    }

    // ---- epilogue: weighted atomic accumulate into out ----
    const int er = wm * 32 + (lane >> 2);
    const int ec = h0 + wn * 32 + 2 * (lane & 3);
#pragma unroll
    for (int i = 0; i < 2; i++)
#pragma unroll
        for (int half = 0; half < 2; half++) {
            int rr = er + i * 16 + half * 8;
            if (m0 + rr < cnt) {
                int   id = rid_s[rr];
                float w  = g_wpair[id];
                float* op = out + (size_t)(id >> 1) * HH + ec;
#pragma unroll
                for (int j = 0; j < 4; j++) {
                    atomicAdd(&op[j * 8],     w * acc[i][j][half * 2 + 0]);
                    atomicAdd(&op[j * 8 + 1], w * acc[i][j][half * 2 + 1]);
                }
            }
        }
}

// ---------------- launch ----------------
extern "C" void kernel_launch(void* const* d_in, const int* in_sizes, int n_in,
                              void* d_out, int out_size) {
    const float* x  = (const float*)d_in[0];
    const float* gw = (const float*)d_in[1];
    const float* wu = (const float*)d_in[2];
    const float* wg = (const float*)d_in[3];
    const float* wd = (const float*)d_in[4];
    float* out = (float*)d_out;

    cudaFuncSetAttribute(stage1_mma, cudaFuncAttributeMaxDynamicSharedMemorySize, SMEM1);
    cudaFuncSetAttribute(stage2_mma, cudaFuncAttributeMaxDynamicSharedMemorySize, SMEM2);

    int n4 = out_size / 4;
    zero_kernel<<<(n4 + 255) / 256, 256>>>((float4*)out, n4);
    split_kernel<<<NW / 4 / 256, 256>>>((const float4*)wu, 0, NW / 4);
    split_kernel<<<NW / 4 / 256, 256>>>((const float4*)wg, 1, NW / 4);
    split_kernel<<<ND / 4 / 256, 256>>>((const float4*)wd, 2, ND / 4);
    split_kernel<<<TT * HH / 4 / 256, 256>>>((const float4*)x, 3, TT * HH / 4);
    router_kernel<<<TT, 128>>>(x, gw);
    stage1_mma<<<dim3(FF / 64, EE * 32), 256, SMEM1>>>();
    stage2_mma<<<dim3(HH / 64, EE * 32), 256, SMEM2>>>(out);
}